// round 12
// baseline (speedup 1.0000x reference)
#include <cuda_runtime.h>
#include <cuda_bf16.h>

// GraphSAGE 2-layer, N=100000, E=1600000, D=128.
// R12: R10 base (565.9us) + layer GEMM split into self-GEMM (feat@Wr^T+b) and
// mean-GEMM (accumulate mean@Wl^T, relu) — self-GEMMs run on a second
// captured stream, overlapping build+agg1 and agg2 respectively.

#define N_NODES 100000
#define N_EDGES 1600000
#define DFEAT   128
#define SCAN_BLK 1024
#define MAX_SCAN_BLOCKS ((N_NODES + SCAN_BLK - 1) / SCAN_BLK + 1)

// ---------------- scratch (device globals; no allocation allowed) ----------
__device__ int   g_is_i64;
__device__ int   g_src[N_EDGES];
__device__ int   g_dst[N_EDGES];
__device__ int   g_cursor[N_NODES];
__device__ int   g_rowptr[N_NODES + 1];
__device__ int   g_col[N_EDGES];
__device__ int   g_bsum[MAX_SCAN_BLOCKS];
__device__ float g_mean[(size_t)N_NODES * DFEAT];
__device__ float g_h[(size_t)N_NODES * DFEAT];

// ---------------- small helpers -------------------------------------------
__device__ __forceinline__ unsigned long long dup_f32x2(float a) {
    unsigned long long r;
    asm("mov.b64 %0, {%1, %1};" : "=l"(r) : "f"(a));
    return r;
}
__device__ __forceinline__ void unpack_f32x2(unsigned long long v, float& lo, float& hi) {
    asm("mov.b64 {%0, %1}, %2;" : "=f"(lo), "=f"(hi) : "l"(v));
}
#define FFMA2(d, a, b, c) \
    asm("fma.rn.f32x2 %0, %1, %2, %3;" : "=l"(d) : "l"(a), "l"(b), "l"(c))

__device__ __forceinline__ int clamp_node(int v, int n) {
    unsigned u = (unsigned)v;
    return (u < (unsigned)n) ? v : 0;
}

// ---------------- edge dtype detect + (extract + degree count) -------------
__global__ void detect_kernel(const int* __restrict__ ew) {
    int flag = 0;
    for (int i = 1; i < 128; i += 2) flag |= ew[i];
    g_is_i64 = (flag == 0) ? 1 : 0;
}

__global__ void convert_count_kernel(const int* __restrict__ ew, int nedges, int nnodes) {
    int e = blockIdx.x * blockDim.x + threadIdx.x;
    if (e >= nedges) return;
    int s, d;
    if (g_is_i64) {
        s = ew[2 * (size_t)e];
        d = ew[2 * ((size_t)nedges + e)];
    } else {
        s = ew[e];
        d = ew[(size_t)nedges + e];
    }
    s = clamp_node(s, nnodes);
    d = clamp_node(d, nnodes);
    g_src[e] = s;
    g_dst[e] = d;
    atomicAdd(&g_cursor[d], 1);
}

__global__ void zero_int_kernel(int* p, int n) {
    int i = blockIdx.x * blockDim.x + threadIdx.x;
    if (i < n) p[i] = 0;
}

// ---------------- parallel scan: 3 phases ----------------------------------
__global__ void __launch_bounds__(SCAN_BLK)
scan_partial_kernel(int n) {
    __shared__ int warp_sums[32];
    int i = blockIdx.x * SCAN_BLK + threadIdx.x;
    int lane = threadIdx.x & 31;
    int wid = threadIdx.x >> 5;
    int v = (i < n) ? g_cursor[i] : 0;
    int x = v;
#pragma unroll
    for (int o = 1; o < 32; o <<= 1) {
        int y = __shfl_up_sync(0xffffffffu, x, o);
        if (lane >= o) x += y;
    }
    if (lane == 31) warp_sums[wid] = x;
    __syncthreads();
    if (wid == 0) {
        int s = warp_sums[lane];
#pragma unroll
        for (int o = 1; o < 32; o <<= 1) {
            int y = __shfl_up_sync(0xffffffffu, s, o);
            if (lane >= o) s += y;
        }
        warp_sums[lane] = s;
    }
    __syncthreads();
    int base = (wid > 0) ? warp_sums[wid - 1] : 0;
    if (i < n) g_rowptr[i] = base + x - v;
    if (threadIdx.x == SCAN_BLK - 1) g_bsum[blockIdx.x] = base + x;
}

__global__ void __launch_bounds__(SCAN_BLK)
scan_bsums_kernel(int nblocks, int n) {
    __shared__ int warp_sums[32];
    int t = threadIdx.x;
    int lane = t & 31;
    int wid = t >> 5;
    int v = (t < nblocks) ? g_bsum[t] : 0;
    int x = v;
#pragma unroll
    for (int o = 1; o < 32; o <<= 1) {
        int y = __shfl_up_sync(0xffffffffu, x, o);
        if (lane >= o) x += y;
    }
    if (lane == 31) warp_sums[wid] = x;
    __syncthreads();
    if (wid == 0) {
        int s = warp_sums[lane];
#pragma unroll
        for (int o = 1; o < 32; o <<= 1) {
            int y = __shfl_up_sync(0xffffffffu, s, o);
            if (lane >= o) s += y;
        }
        warp_sums[lane] = s;
    }
    __syncthreads();
    int base = (wid > 0) ? warp_sums[wid - 1] : 0;
    if (t < nblocks) g_bsum[t] = base + x - v;
    if (t == SCAN_BLK - 1) g_rowptr[n] = base + x;
}

__global__ void __launch_bounds__(SCAN_BLK)
scan_add_kernel(int n) {
    int i = blockIdx.x * SCAN_BLK + threadIdx.x;
    if (i >= n) return;
    g_rowptr[i] += g_bsum[blockIdx.x];
    g_cursor[i] = 0;
}

__global__ void fill_csr_kernel(int nedges) {
    int e = blockIdx.x * blockDim.x + threadIdx.x;
    if (e >= nedges) return;
    int dst = g_dst[e];
    int pos = g_rowptr[dst] + atomicAdd(&g_cursor[dst], 1);
    g_col[pos] = g_src[e];
}

// ---------------- mean aggregation: one warp per node (R10 4-wide) ---------
__global__ void agg_mean_kernel(const float* __restrict__ feat, int nnodes) {
    int gwarp = (blockIdx.x * blockDim.x + threadIdx.x) >> 5;
    int lane = threadIdx.x & 31;
    if (gwarp >= nnodes) return;

    int start = g_rowptr[gwarp];
    int end = g_rowptr[gwarp + 1];
    float ax = 0.f, ay = 0.f, az = 0.f, aw = 0.f;
    int lane4 = lane * 4;

    for (int base = start; base < end; base += 32) {
        int m = min(32, end - base);
        int sv = (lane < m) ? g_col[base + lane] : 0;
        int kk = 0;
        for (; kk + 4 <= m; kk += 4) {
            int s0 = __shfl_sync(0xffffffffu, sv, kk);
            int s1 = __shfl_sync(0xffffffffu, sv, kk + 1);
            int s2 = __shfl_sync(0xffffffffu, sv, kk + 2);
            int s3 = __shfl_sync(0xffffffffu, sv, kk + 3);
            float4 v0 = *reinterpret_cast<const float4*>(feat + (size_t)s0 * DFEAT + lane4);
            float4 v1 = *reinterpret_cast<const float4*>(feat + (size_t)s1 * DFEAT + lane4);
            float4 v2 = *reinterpret_cast<const float4*>(feat + (size_t)s2 * DFEAT + lane4);
            float4 v3 = *reinterpret_cast<const float4*>(feat + (size_t)s3 * DFEAT + lane4);
            ax += v0.x + v1.x + v2.x + v3.x;
            ay += v0.y + v1.y + v2.y + v3.y;
            az += v0.z + v1.z + v2.z + v3.z;
            aw += v0.w + v1.w + v2.w + v3.w;
        }
        for (; kk < m; ++kk) {
            int s = __shfl_sync(0xffffffffu, sv, kk);
            float4 v = *reinterpret_cast<const float4*>(feat + (size_t)s * DFEAT + lane4);
            ax += v.x; ay += v.y; az += v.z; aw += v.w;
        }
    }
    float inv = 1.f / fmaxf((float)(end - start), 1.f);
    float4 o;
    o.x = ax * inv; o.y = ay * inv; o.z = az * inv; o.w = aw * inv;
    *reinterpret_cast<float4*>(g_mean + (size_t)gwarp * DFEAT + lane4) = o;
}

// ---------------- persistent half GEMM (K=128) -------------------------------
// accum=0: out[n][j] = A[n][k]*W[j][k] + bias[j]          (self half)
// accum=1: out[n][j] = [relu](out[n][j] + A[n][k]*W[j][k]) (mean half)
// grid=148 persistent CTAs x 512 threads; 128-node tiles; double-buffered
// dup-A staging; inner loop: 4x uniform LDS.128 (A) + 1x LDS.128 (W) +
// 16x FFMA2 per k.
#define W_STRIDE 132
#define GTILE    128
#define HGEMM_SMEM (128 * W_STRIDE * 4 + 2 * 32 * 128 * 8)

__global__ void __launch_bounds__(512)
half_gemm_kernel(const float* __restrict__ A,
                 const float* __restrict__ W,
                 const float* __restrict__ bias,
                 float* __restrict__ out,
                 int nnodes, int relu, int accum, int ntiles) {
    extern __shared__ float smem[];
    float* sW = smem;                                                   // 128*132
    unsigned long long* sA2 =
        reinterpret_cast<unsigned long long*>(smem + 128 * W_STRIDE);   // 2*32*128

    int tid = threadIdx.x;
    // Load + transpose weights ONCE per CTA.
    for (int idx = tid; idx < 128 * 128; idx += 512) {
        int j = idx >> 7;
        int k = idx & 127;
        sW[k * W_STRIDE + j] = W[idx];
    }

    int lane = tid & 31;
    int warp = tid >> 5;
    int j0 = lane * 4;

    int st_node = tid >> 2;           // 0..127
    int st_q = tid & 3;               // 0..3 -> k offsets q*8..q*8+7
    int kb = st_q * 8;

    // init value for accumulators
    unsigned long long b01 = 0, b23 = 0;
    if (!accum) {
        float4 bv = *reinterpret_cast<const float4*>(bias + j0);
        asm("mov.b64 %0, {%1, %2};" : "=l"(b01) : "f"(bv.x), "f"(bv.y));
        asm("mov.b64 %0, {%1, %2};" : "=l"(b23) : "f"(bv.z), "f"(bv.w));
    }

    for (int tile = blockIdx.x; tile < ntiles; tile += gridDim.x) {
        int base_node = tile * GTILE;
        int st_gnode = base_node + st_node;
        if (st_gnode >= nnodes) st_gnode = nnodes - 1;
        const float* ap = A + (size_t)st_gnode * DFEAT + st_q * 8;

        // prefetch chunk 0
        float4 v0 = *reinterpret_cast<const float4*>(ap);
        float4 v1 = *reinterpret_cast<const float4*>(ap + 4);

        unsigned long long acc[16];
#pragma unroll
        for (int m = 0; m < 8; ++m) { acc[2 * m] = b01; acc[2 * m + 1] = b23; }

        for (int c = 0; c < 4; ++c) {
            unsigned long long* buf = sA2 + (c & 1) * (32 * 128);
            buf[(kb + 0) * 128 + st_node] = dup_f32x2(v0.x);
            buf[(kb + 1) * 128 + st_node] = dup_f32x2(v0.y);
            buf[(kb + 2) * 128 + st_node] = dup_f32x2(v0.z);
            buf[(kb + 3) * 128 + st_node] = dup_f32x2(v0.w);
            buf[(kb + 4) * 128 + st_node] = dup_f32x2(v1.x);
            buf[(kb + 5) * 128 + st_node] = dup_f32x2(v1.y);
            buf[(kb + 6) * 128 + st_node] = dup_f32x2(v1.z);
            buf[(kb + 7) * 128 + st_node] = dup_f32x2(v1.w);

            if (c + 1 < 4) {
                int koff = (c + 1) * 32;
                v0 = *reinterpret_cast<const float4*>(ap + koff);
                v1 = *reinterpret_cast<const float4*>(ap + koff + 4);
            }
            __syncthreads();

            int krow = c * 32;
            const unsigned long long* aw_base = buf + warp * 8;
#pragma unroll 4
            for (int kk = 0; kk < 32; ++kk) {
                ulonglong2 wv = *reinterpret_cast<const ulonglong2*>(
                    &sW[(krow + kk) * W_STRIDE + j0]);
                const ulonglong2* ar2 =
                    reinterpret_cast<const ulonglong2*>(aw_base + kk * 128);
                ulonglong2 a01 = ar2[0];
                ulonglong2 a23 = ar2[1];
                ulonglong2 a45 = ar2[2];
                ulonglong2 a67 = ar2[3];
                FFMA2(acc[0],  a01.x, wv.x, acc[0]);
                FFMA2(acc[1],  a01.x, wv.y, acc[1]);
                FFMA2(acc[2],  a01.y, wv.x, acc[2]);
                FFMA2(acc[3],  a01.y, wv.y, acc[3]);
                FFMA2(acc[4],  a23.x, wv.x, acc[4]);
                FFMA2(acc[5],  a23.x, wv.y, acc[5]);
                FFMA2(acc[6],  a23.y, wv.x, acc[6]);
                FFMA2(acc[7],  a23.y, wv.y, acc[7]);
                FFMA2(acc[8],  a45.x, wv.x, acc[8]);
                FFMA2(acc[9],  a45.x, wv.y, acc[9]);
                FFMA2(acc[10], a45.y, wv.x, acc[10]);
                FFMA2(acc[11], a45.y, wv.y, acc[11]);
                FFMA2(acc[12], a67.x, wv.x, acc[12]);
                FFMA2(acc[13], a67.x, wv.y, acc[13]);
                FFMA2(acc[14], a67.y, wv.x, acc[14]);
                FFMA2(acc[15], a67.y, wv.y, acc[15]);
            }
        }

        int wnode = base_node + warp * 8;
#pragma unroll
        for (int m = 0; m < 8; ++m) {
            int nd = wnode + m;
            if (nd >= nnodes) break;
            float4 o;
            unpack_f32x2(acc[2 * m], o.x, o.y);
            unpack_f32x2(acc[2 * m + 1], o.z, o.w);
            float* optr = out + (size_t)nd * DFEAT + j0;
            if (accum) {
                float4 prev = *reinterpret_cast<const float4*>(optr);
                o.x += prev.x; o.y += prev.y; o.z += prev.z; o.w += prev.w;
            }
            if (relu) {
                o.x = fmaxf(o.x, 0.f); o.y = fmaxf(o.y, 0.f);
                o.z = fmaxf(o.z, 0.f); o.w = fmaxf(o.w, 0.f);
            }
            *reinterpret_cast<float4*>(optr) = o;
        }
        __syncthreads();   // tile done before next staging overwrites buffers
    }
}

// ---------------- launch ----------------------------------------------------
extern "C" void kernel_launch(void* const* d_in, const int* in_sizes, int n_in,
                              void* d_out, int out_size) {
    const float* x   = (const float*)d_in[0];
    const int*   ew  = (const int*)d_in[1];
    const float* Wl1 = (const float*)d_in[2];
    const float* bl1 = (const float*)d_in[3];
    const float* Wr1 = (const float*)d_in[4];
    const float* Wl2 = (const float*)d_in[5];
    const float* bl2 = (const float*)d_in[6];
    const float* Wr2 = (const float*)d_in[7];
    float*       out = (float*)d_out;

    int n = in_sizes[0] / DFEAT;      // 100000
    int e = in_sizes[1] / 2;          // 1600000

    void *p_mean_v, *p_h_v, *p_cursor_v;
    cudaGetSymbolAddress(&p_mean_v, g_mean);
    cudaGetSymbolAddress(&p_h_v, g_h);
    cudaGetSymbolAddress(&p_cursor_v, g_cursor);
    float* p_mean = (float*)p_mean_v;
    float* p_h = (float*)p_h_v;
    int* p_cursor = (int*)p_cursor_v;

    // side stream + events (created once; host resources only, no device mem)
    static cudaStream_t s2 = nullptr;
    static cudaEvent_t evRoot = nullptr, evSelf1 = nullptr,
                       evMean1 = nullptr, evSelf2 = nullptr;
    if (!s2) {
        cudaStreamCreateWithFlags(&s2, cudaStreamNonBlocking);
        cudaEventCreateWithFlags(&evRoot, cudaEventDisableTiming);
        cudaEventCreateWithFlags(&evSelf1, cudaEventDisableTiming);
        cudaEventCreateWithFlags(&evMean1, cudaEventDisableTiming);
        cudaEventCreateWithFlags(&evSelf2, cudaEventDisableTiming);
        cudaFuncSetAttribute(half_gemm_kernel,
                             cudaFuncAttributeMaxDynamicSharedMemorySize, HGEMM_SMEM);
    }

    int zb = (n + 255) / 256;
    int eb = (e + 255) / 256;
    int ab = (n + 7) / 8;
    int sb = (n + SCAN_BLK - 1) / SCAN_BLK;
    int ntiles = (n + GTILE - 1) / GTILE;

    // fork: self-GEMM1 on s2 (depends only on x / Wr1 / bl1)
    cudaEventRecord(evRoot, 0);
    cudaStreamWaitEvent(s2, evRoot, 0);
    half_gemm_kernel<<<148, 512, HGEMM_SMEM, s2>>>(
        x, Wr1, bl1, p_h, n, /*relu=*/0, /*accum=*/0, ntiles);
    cudaEventRecord(evSelf1, s2);

    // main stream: CSR build + agg1
    detect_kernel<<<1, 1>>>(ew);
    zero_int_kernel<<<zb, 256>>>(p_cursor, n);
    convert_count_kernel<<<eb, 256>>>(ew, e, n);
    scan_partial_kernel<<<sb, SCAN_BLK>>>(n);
    scan_bsums_kernel<<<1, SCAN_BLK>>>(sb, n);
    scan_add_kernel<<<sb, SCAN_BLK>>>(n);
    fill_csr_kernel<<<eb, 256>>>(e);
    agg_mean_kernel<<<ab, 256>>>(x, n);

    // join: mean-GEMM1 accumulates into p_h (needs agg1 + selfgemm1), relu
    cudaStreamWaitEvent(0, evSelf1, 0);
    half_gemm_kernel<<<148, 512, HGEMM_SMEM>>>(
        p_mean, Wl1, bl1, p_h, n, /*relu=*/1, /*accum=*/1, ntiles);
    cudaEventRecord(evMean1, 0);

    // fork: self-GEMM2 on s2 (needs p_h)
    cudaStreamWaitEvent(s2, evMean1, 0);
    half_gemm_kernel<<<148, 512, HGEMM_SMEM, s2>>>(
        p_h, Wr2, bl2, out, n, /*relu=*/0, /*accum=*/0, ntiles);
    cudaEventRecord(evSelf2, s2);

    // main stream: agg2 (needs p_h, ordered after meangemm1)
    agg_mean_kernel<<<ab, 256>>>(p_h, n);

    // join: mean-GEMM2 accumulates into out
    cudaStreamWaitEvent(0, evSelf2, 0);
    half_gemm_kernel<<<148, 512, HGEMM_SMEM>>>(
        p_mean, Wl2, bl2, out, n, /*relu=*/0, /*accum=*/1, ntiles);
}